// round 2
// baseline (speedup 1.0000x reference)
#include <cuda_runtime.h>

#define HH 2048
#define WW 2048
#define NB 1024

// Scratch (no cudaMalloc allowed): compacted valid boxes.
__device__ ushort4 g_bounds[NB];   // {y1, x1, y2, x2} pixel-space, clamped
__device__ float4  g_vals[NB];     // original normalized box coords (channels 1..4)
__device__ int     g_count;

// ---------------------------------------------------------------------------
// Kernel 1: compute pixel bounds per box, compact valid boxes preserving order.
// One block, 1024 threads.
// ---------------------------------------------------------------------------
__global__ void prep_kernel(const float* __restrict__ boxes) {
    int i = threadIdx.x;
    float b0 = boxes[4 * i + 0];
    float b1 = boxes[4 * i + 1];
    float b2 = boxes[4 * i + 2];
    float b3 = boxes[4 * i + 3];

    // match reference: truncate toward zero, then clamp
    int y1 = max(0,  (int)(b0 * (float)HH));
    int x1 = max(0,  (int)(b1 * (float)WW));
    int y2 = min(HH, (int)(b2 * (float)HH));
    int x2 = min(WW, (int)(b3 * (float)WW));

    bool valid = (y1 < y2) && (x1 < x2);

    unsigned mask = __ballot_sync(0xffffffffu, valid);
    int lane = i & 31;
    int warp = i >> 5;
    int wprefix = __popc(mask & ((1u << lane) - 1u));

    __shared__ int wtot[32];
    __shared__ int wbase[32];
    if (lane == 0) wtot[warp] = __popc(mask);
    __syncthreads();
    if (i == 0) {
        int s = 0;
        for (int w = 0; w < 32; ++w) { wbase[w] = s; s += wtot[w]; }
        g_count = s;
    }
    __syncthreads();

    if (valid) {
        int pos = wbase[warp] + wprefix;  // order-preserving compaction
        g_bounds[pos] = make_ushort4((unsigned short)y1, (unsigned short)x1,
                                     (unsigned short)y2, (unsigned short)x2);
        g_vals[pos] = make_float4(b0, b1, b2, b3);
    }
}

// ---------------------------------------------------------------------------
// Kernel 2: per-pixel last-covering-box search. 4 pixels (x) per thread.
// blockDim = (64, 4): tile = 256 x 4 pixels. Grid = (8, 512).
// ---------------------------------------------------------------------------
__global__ void __launch_bounds__(256) paint_kernel(float* __restrict__ out) {
    __shared__ ushort4 sb[NB];
    __shared__ float4  sv[NB];

    int n = g_count;
    int tid = threadIdx.y * blockDim.x + threadIdx.x;
    for (int i = tid; i < n; i += 256) {
        sb[i] = g_bounds[i];
        sv[i] = g_vals[i];
    }
    __syncthreads();

    int x0 = (blockIdx.x * blockDim.x + threadIdx.x) * 4;
    int y  = blockIdx.y * blockDim.y + threadIdx.y;

    int i0 = -1, i1 = -1, i2 = -1, i3 = -1;
    for (int i = n - 1; i >= 0; --i) {
        ushort4 b = sb[i];          // warp-uniform broadcast load
        int by1 = b.x, bx1 = b.y, by2 = b.z, bx2 = b.w;
        if (y >= by1 && y < by2) {
            if (i0 < 0 && (x0    ) >= bx1 && (x0    ) < bx2) i0 = i;
            if (i1 < 0 && (x0 + 1) >= bx1 && (x0 + 1) < bx2) i1 = i;
            if (i2 < 0 && (x0 + 2) >= bx1 && (x0 + 2) < bx2) i2 = i;
            if (i3 < 0 && (x0 + 3) >= bx1 && (x0 + 3) < bx2) i3 = i;
        }
        // all four found?  (-1 has sign bit set; OR >= 0 iff none is -1)
        if ((i0 | i1 | i2 | i3) >= 0) break;
    }

    float4 v0 = (i0 >= 0) ? sv[i0] : make_float4(0.f, 0.f, 0.f, 0.f);
    float4 v1 = (i1 >= 0) ? sv[i1] : make_float4(0.f, 0.f, 0.f, 0.f);
    float4 v2 = (i2 >= 0) ? sv[i2] : make_float4(0.f, 0.f, 0.f, 0.f);
    float4 v3 = (i3 >= 0) ? sv[i3] : make_float4(0.f, 0.f, 0.f, 0.f);

    float4 c0 = make_float4(i0 >= 0 ? 1.f : 0.f,
                            i1 >= 0 ? 1.f : 0.f,
                            i2 >= 0 ? 1.f : 0.f,
                            i3 >= 0 ? 1.f : 0.f);
    float4 c1 = make_float4(v0.x, v1.x, v2.x, v3.x);
    float4 c2 = make_float4(v0.y, v1.y, v2.y, v3.y);
    float4 c3 = make_float4(v0.z, v1.z, v2.z, v3.z);
    float4 c4 = make_float4(v0.w, v1.w, v2.w, v3.w);

    const size_t HWsz = (size_t)HH * (size_t)WW;
    size_t base = (size_t)y * WW + (size_t)x0;
    *(float4*)(out + 0 * HWsz + base) = c0;
    *(float4*)(out + 1 * HWsz + base) = c1;
    *(float4*)(out + 2 * HWsz + base) = c2;
    *(float4*)(out + 3 * HWsz + base) = c3;
    *(float4*)(out + 4 * HWsz + base) = c4;
}

extern "C" void kernel_launch(void* const* d_in, const int* in_sizes, int n_in,
                              void* d_out, int out_size) {
    const float* boxes = (const float*)d_in[0];
    float* out = (float*)d_out;

    prep_kernel<<<1, NB>>>(boxes);

    dim3 block(64, 4);
    dim3 grid(WW / (64 * 4), HH / 4);  // (8, 512)
    paint_kernel<<<grid, block>>>(out);
}

// round 3
// speedup vs baseline: 3.5813x; 3.5813x over previous
#include <cuda_runtime.h>

#define HH 2048
#define WW 2048
#define NB 1024

#define TW 128   // tile width (pixels)
#define TH 16    // tile height (pixels)
#define BT 512   // threads per block (32 x 16)

// Scratch (no cudaMalloc allowed): compacted valid boxes.
__device__ ushort4 g_bounds[NB];   // {y1, x1, y2, x2} pixel-space, clamped
__device__ float4  g_vals[NB];     // original normalized box coords (channels 1..4)
__device__ int     g_count;

// ---------------------------------------------------------------------------
// Kernel 1: compute pixel bounds per box, compact valid boxes preserving order.
// One block, 1024 threads.
// ---------------------------------------------------------------------------
__global__ void prep_kernel(const float* __restrict__ boxes) {
    int i = threadIdx.x;
    float b0 = boxes[4 * i + 0];
    float b1 = boxes[4 * i + 1];
    float b2 = boxes[4 * i + 2];
    float b3 = boxes[4 * i + 3];

    // match reference: truncate toward zero, then clamp
    int y1 = max(0,  (int)(b0 * (float)HH));
    int x1 = max(0,  (int)(b1 * (float)WW));
    int y2 = min(HH, (int)(b2 * (float)HH));
    int x2 = min(WW, (int)(b3 * (float)WW));

    bool valid = (y1 < y2) && (x1 < x2);

    unsigned mask = __ballot_sync(0xffffffffu, valid);
    int lane = i & 31;
    int warp = i >> 5;
    int wprefix = __popc(mask & ((1u << lane) - 1u));

    __shared__ int wtot[32];
    __shared__ int wbase[32];
    if (lane == 0) wtot[warp] = __popc(mask);
    __syncthreads();
    if (i == 0) {
        int s = 0;
        for (int w = 0; w < 32; ++w) { wbase[w] = s; s += wtot[w]; }
        g_count = s;
    }
    __syncthreads();

    if (valid) {
        int pos = wbase[warp] + wprefix;  // order-preserving compaction
        g_bounds[pos] = make_ushort4((unsigned short)y1, (unsigned short)x1,
                                     (unsigned short)y2, (unsigned short)x2);
        g_vals[pos] = make_float4(b0, b1, b2, b3);
    }
}

// ---------------------------------------------------------------------------
// Kernel 2: one block per 128x16 tile. Cooperative descending-order compaction
// of tile-intersecting boxes into shared, with early stop at the first
// fully-tile-covering box. Then a short per-pixel first-hit scan.
// ---------------------------------------------------------------------------
__global__ void __launch_bounds__(BT) paint_kernel(float* __restrict__ out) {
    __shared__ ushort4 sb[NB];        // 8 KB
    __shared__ float4  sv[NB];        // 16 KB
    __shared__ int s_len, s_stop;
    __shared__ int wcnt[BT / 32], woff[BT / 32];

    const int n    = g_count;
    const int tid  = threadIdx.y * 32 + threadIdx.x;
    const int wid  = tid >> 5;
    const int lane = tid & 31;

    const int tx0 = blockIdx.x * TW;
    const int ty0 = blockIdx.y * TH;
    const int tx1 = tx0 + TW;
    const int ty1 = ty0 + TH;

    if (tid == 0) { s_len = 0; s_stop = 0; }
    __syncthreads();

    // Descending-index chunks of BT boxes; stable block-wide compaction.
    for (int base = n - 1; base >= 0; base -= BT) {
        int i = base - tid;               // tid 0 takes the highest index
        bool inter = false, full = false;
        ushort4 b;
        float4  v;
        if (i >= 0) {
            b = g_bounds[i];
            inter = (b.x < ty1) && (b.z > ty0) && (b.y < tx1) && (b.w > tx0);
            if (inter) {
                v = g_vals[i];
                full = (b.x <= ty0) && (b.z >= ty1) && (b.y <= tx0) && (b.w >= tx1);
            }
        }
        unsigned m = __ballot_sync(0xffffffffu, inter);
        if (lane == 0) wcnt[wid] = __popc(m);
        __syncthreads();
        if (tid == 0) {
            int s = s_len;
            #pragma unroll
            for (int w = 0; w < BT / 32; ++w) { woff[w] = s; s += wcnt[w]; }
            s_len = s;
        }
        __syncthreads();
        if (inter) {
            int pos = woff[wid] + __popc(m & ((1u << lane) - 1u));
            sb[pos] = b;
            sv[pos] = v;
            if (full) s_stop = 1;         // races are fine, value only goes to 1
        }
        __syncthreads();
        if (s_stop) break;                // everything below is unreachable
    }

    const int len = s_len;

    const int x0 = tx0 + threadIdx.x * 4;
    const int y  = ty0 + threadIdx.y;

    int i0 = -1, i1 = -1, i2 = -1, i3 = -1;
    for (int j = 0; j < len; ++j) {
        ushort4 b = sb[j];                // warp-uniform broadcast load
        if (y >= b.x && y < b.z) {
            if (i0 < 0 && (x0    ) >= b.y && (x0    ) < b.w) i0 = j;
            if (i1 < 0 && (x0 + 1) >= b.y && (x0 + 1) < b.w) i1 = j;
            if (i2 < 0 && (x0 + 2) >= b.y && (x0 + 2) < b.w) i2 = j;
            if (i3 < 0 && (x0 + 3) >= b.y && (x0 + 3) < b.w) i3 = j;
        }
        if ((i0 | i1 | i2 | i3) >= 0) break;   // all four found
    }

    float4 v0 = (i0 >= 0) ? sv[i0] : make_float4(0.f, 0.f, 0.f, 0.f);
    float4 v1 = (i1 >= 0) ? sv[i1] : make_float4(0.f, 0.f, 0.f, 0.f);
    float4 v2 = (i2 >= 0) ? sv[i2] : make_float4(0.f, 0.f, 0.f, 0.f);
    float4 v3 = (i3 >= 0) ? sv[i3] : make_float4(0.f, 0.f, 0.f, 0.f);

    float4 c0 = make_float4(i0 >= 0 ? 1.f : 0.f,
                            i1 >= 0 ? 1.f : 0.f,
                            i2 >= 0 ? 1.f : 0.f,
                            i3 >= 0 ? 1.f : 0.f);
    float4 c1 = make_float4(v0.x, v1.x, v2.x, v3.x);
    float4 c2 = make_float4(v0.y, v1.y, v2.y, v3.y);
    float4 c3 = make_float4(v0.z, v1.z, v2.z, v3.z);
    float4 c4 = make_float4(v0.w, v1.w, v2.w, v3.w);

    const size_t HWsz = (size_t)HH * (size_t)WW;
    size_t base = (size_t)y * WW + (size_t)x0;
    *(float4*)(out + 0 * HWsz + base) = c0;
    *(float4*)(out + 1 * HWsz + base) = c1;
    *(float4*)(out + 2 * HWsz + base) = c2;
    *(float4*)(out + 3 * HWsz + base) = c3;
    *(float4*)(out + 4 * HWsz + base) = c4;
}

extern "C" void kernel_launch(void* const* d_in, const int* in_sizes, int n_in,
                              void* d_out, int out_size) {
    const float* boxes = (const float*)d_in[0];
    float* out = (float*)d_out;

    prep_kernel<<<1, NB>>>(boxes);

    dim3 block(32, 16);                       // 512 threads
    dim3 grid(WW / TW, HH / TH);              // (16, 128) = 2048 blocks
    paint_kernel<<<grid, block>>>(out);
}

// round 4
// speedup vs baseline: 3.7830x; 1.0563x over previous
#include <cuda_runtime.h>

#define HH 2048
#define WW 2048
#define NB 1024

#define TW 128   // tile width (pixels)
#define TH 16    // tile height (pixels)
#define BT 512   // threads per block (32 x 16)

// ---------------------------------------------------------------------------
// Single fused kernel: one block per 128x16 tile.
// Phase 1: cooperative descending-order compaction of valid AND tile-
//          intersecting boxes into shared memory (bounds computed inline from
//          the raw box list), early-stopping at the first box that fully
//          covers the tile (everything painted earlier is unreachable).
// Phase 2: per-pixel first-hit scan (descending paint order == ascending j),
//          software-pipelined shared loads, then 5 coalesced float4 stores.
// ---------------------------------------------------------------------------
__global__ void __launch_bounds__(BT) paint_kernel(const float* __restrict__ boxes,
                                                   float* __restrict__ out) {
    __shared__ ushort4 sb[NB];        // 8 KB  {y1,x1,y2,x2} pixel bounds
    __shared__ float4  sv[NB];        // 16 KB original normalized coords
    __shared__ int s_len, s_stop;
    __shared__ int wcnt[BT / 32], woff[BT / 32];

    const int tid  = threadIdx.y * 32 + threadIdx.x;
    const int wid  = tid >> 5;
    const int lane = tid & 31;

    const int tx0 = blockIdx.x * TW;
    const int ty0 = blockIdx.y * TH;
    const int tx1 = tx0 + TW;
    const int ty1 = ty0 + TH;

    if (tid == 0) { s_len = 0; s_stop = 0; }
    __syncthreads();

    // Two descending chunks of 512 boxes; stable block-wide compaction.
    #pragma unroll
    for (int chunk = 0; chunk < NB / BT; ++chunk) {
        int i = (NB - 1) - chunk * BT - tid;   // tid 0 takes the highest index
        bool inter = false, full = false;
        ushort4 b;
        float4  v;
        {
            v = *(const float4*)(boxes + 4 * i);
            // match reference: truncate toward zero, then clamp
            int y1 = max(0,  (int)(v.x * (float)HH));
            int x1 = max(0,  (int)(v.y * (float)WW));
            int y2 = min(HH, (int)(v.z * (float)HH));
            int x2 = min(WW, (int)(v.w * (float)WW));
            // valid (y1<y2 && x1<x2) is implied by the intersection test
            inter = (y1 < ty1) && (y2 > ty0) && (x1 < tx1) && (x2 > tx0) &&
                    (y1 < y2) && (x1 < x2);
            if (inter) {
                b = make_ushort4((unsigned short)y1, (unsigned short)x1,
                                 (unsigned short)y2, (unsigned short)x2);
                full = (y1 <= ty0) && (y2 >= ty1) && (x1 <= tx0) && (x2 >= tx1);
            }
        }
        unsigned m = __ballot_sync(0xffffffffu, inter);
        if (lane == 0) wcnt[wid] = __popc(m);
        __syncthreads();
        if (tid == 0) {
            int s = s_len;
            #pragma unroll
            for (int w = 0; w < BT / 32; ++w) { woff[w] = s; s += wcnt[w]; }
            s_len = s;
        }
        __syncthreads();
        if (inter) {
            int pos = woff[wid] + __popc(m & ((1u << lane) - 1u));
            sb[pos] = b;
            sv[pos] = v;
            if (full) s_stop = 1;         // benign race, value only goes to 1
        }
        __syncthreads();
        if (s_stop) break;                // everything below is unreachable
    }

    const int len = s_len;

    const int x0 = tx0 + threadIdx.x * 4;
    const int y  = ty0 + threadIdx.y;     // warp-uniform

    int i0 = -1, i1 = -1, i2 = -1, i3 = -1;
    if (len > 0) {
        ushort4 b = sb[0];
        for (int j = 0; j < len; ++j) {
            ushort4 bn = sb[(j + 1 < len) ? j + 1 : j];   // prefetch next
            if (y >= b.x && y < b.z) {                    // warp-uniform test
                if (i0 < 0 && (x0    ) >= b.y && (x0    ) < b.w) i0 = j;
                if (i1 < 0 && (x0 + 1) >= b.y && (x0 + 1) < b.w) i1 = j;
                if (i2 < 0 && (x0 + 2) >= b.y && (x0 + 2) < b.w) i2 = j;
                if (i3 < 0 && (x0 + 3) >= b.y && (x0 + 3) < b.w) i3 = j;
            }
            if ((i0 | i1 | i2 | i3) >= 0) break;          // all four found
            b = bn;
        }
    }

    float4 v0 = (i0 >= 0) ? sv[i0] : make_float4(0.f, 0.f, 0.f, 0.f);
    float4 v1 = (i1 >= 0) ? sv[i1] : make_float4(0.f, 0.f, 0.f, 0.f);
    float4 v2 = (i2 >= 0) ? sv[i2] : make_float4(0.f, 0.f, 0.f, 0.f);
    float4 v3 = (i3 >= 0) ? sv[i3] : make_float4(0.f, 0.f, 0.f, 0.f);

    float4 c0 = make_float4(i0 >= 0 ? 1.f : 0.f,
                            i1 >= 0 ? 1.f : 0.f,
                            i2 >= 0 ? 1.f : 0.f,
                            i3 >= 0 ? 1.f : 0.f);
    float4 c1 = make_float4(v0.x, v1.x, v2.x, v3.x);
    float4 c2 = make_float4(v0.y, v1.y, v2.y, v3.y);
    float4 c3 = make_float4(v0.z, v1.z, v2.z, v3.z);
    float4 c4 = make_float4(v0.w, v1.w, v2.w, v3.w);

    const size_t HWsz = (size_t)HH * (size_t)WW;
    size_t base = (size_t)y * WW + (size_t)x0;
    *(float4*)(out + 0 * HWsz + base) = c0;
    *(float4*)(out + 1 * HWsz + base) = c1;
    *(float4*)(out + 2 * HWsz + base) = c2;
    *(float4*)(out + 3 * HWsz + base) = c3;
    *(float4*)(out + 4 * HWsz + base) = c4;
}

extern "C" void kernel_launch(void* const* d_in, const int* in_sizes, int n_in,
                              void* d_out, int out_size) {
    const float* boxes = (const float*)d_in[0];
    float* out = (float*)d_out;

    dim3 block(32, 16);                       // 512 threads
    dim3 grid(WW / TW, HH / TH);              // (16, 128) = 2048 blocks
    paint_kernel<<<grid, block>>>(boxes, out);
}